// round 3
// baseline (speedup 1.0000x reference)
#include <cuda_runtime.h>
#include <cuda_bf16.h>

#define THR_LO 0.6f
#define THR_HI 0.8f

#define GRID_BLOCKS 1184   // 148 SMs * 8 CTAs (256 thr) = exactly one full wave
#define BLOCK_THREADS 256

// Per-block partials: n_sim, n_disim, sim_sum, disim_sum. Each block writes
// its own slot -> no init kernel needed.
__device__ double g_part[GRID_BLOCKS][4];

__global__ void __launch_bounds__(BLOCK_THREADS)
lp_edge_kernel(const void* __restrict__ edges,
               const float* __restrict__ probas,
               const float* __restrict__ feats,
               int n_edges, int n_nodes) {
    __shared__ int sh_is64;
    if (threadIdx.x == 0) {
        // int64 indices (< 2^31) have zero high words at odd 32-bit positions.
        // For int32 edges, words 1,3,5,7 are j0,i1,j1,i2 — all-zero prob ~1e-20.
        const int4* w = reinterpret_cast<const int4*>(edges);
        int4 a = __ldg(&w[0]);  // words 0..3
        int4 b = __ldg(&w[1]);  // words 4..7
        sh_is64 = ((a.y | a.w | b.y | b.w) == 0) ? 1 : 0;
    }
    __syncthreads();
    const int is64 = sh_is64;

    const longlong2* e64 = reinterpret_cast<const longlong2*>(edges);
    const int2* e32 = reinterpret_cast<const int2*>(edges);

    float n_sim = 0.f, n_dis = 0.f, s_sim = 0.f, s_dis = 0.f;

    const int lane = threadIdx.x & 31;
    const int stride = GRID_BLOCKS * BLOCK_THREADS;
    // Warp-uniform base so all 32 lanes iterate together (shfl-safe).
    int eb0 = blockIdx.x * BLOCK_THREADS + (threadIdx.x & ~31);

    for (int eb = eb0; eb < n_edges; eb += stride) {
        int e = eb + lane;
        bool valid = e < n_edges;

        int i = 0, j = 0;
        if (valid) {
            if (is64) {
                longlong2 ij = e64[e];
                i = (int)ij.x; j = (int)ij.y;
            } else {
                int2 ij = e32[e];
                i = ij.x; j = ij.y;
            }
        }
        // Safety: bad index -> skipped edge (shows as rel_err, not a crash).
        if ((unsigned)i >= (unsigned)n_nodes || (unsigned)j >= (unsigned)n_nodes)
            valid = false;

        bool ms = false, md = false;
        if (valid) {
            float pi = __ldg(&probas[i]);
            float pj = __ldg(&probas[j]);
            ms = (pi >= THR_HI) && (pj >= THR_HI);
            md = ((pi >= THR_HI) && (pj < THR_LO)) ||
                 ((pj >= THR_HI) && (pi < THR_LO));
        }

        unsigned work = __ballot_sync(0xFFFFFFFFu, ms | md);
        // Whole warp cooperates on each masked edge: lanes 0-15 load row i,
        // lanes 16-31 load row j (one float4 each = both 256B rows, coalesced).
        while (work) {
            int src = __ffs(work) - 1;
            work &= work - 1;
            int si = __shfl_sync(0xFFFFFFFFu, i, src);
            int sj = __shfl_sync(0xFFFFFFFFu, j, src);

            int half = lane >> 4;           // 0 -> fi, 1 -> fj
            int k = lane & 15;
            const float4* row = reinterpret_cast<const float4*>(
                feats + (long long)(half ? sj : si) * 64);
            float4 v = __ldg(&row[k]);

            // Pair with the other row's matching chunk (lane ^ 16).
            float ox = __shfl_xor_sync(0xFFFFFFFFu, v.x, 16);
            float oy = __shfl_xor_sync(0xFFFFFFFFu, v.y, 16);
            float oz = __shfl_xor_sync(0xFFFFFFFFu, v.z, 16);
            float ow = __shfl_xor_sync(0xFFFFFFFFu, v.w, 16);

            float dx = v.x - ox, dy = v.y - oy, dz = v.z - oz, dw = v.w - ow;
            float s = fmaf(dx, dx, fmaf(dy, dy, fmaf(dz, dz, dw * dw)));

            // Sum across the 16 chunks (lane^16 already holds identical s).
            s += __shfl_xor_sync(0xFFFFFFFFu, s, 8);
            s += __shfl_xor_sync(0xFFFFFFFFu, s, 4);
            s += __shfl_xor_sync(0xFFFFFFFFu, s, 2);
            s += __shfl_xor_sync(0xFFFFFFFFu, s, 1);

            if (lane == src) {
                float d = sqrtf(s);
                if (ms) {
                    // bce_sim = -max(log(exp(-d)), -100) = min(d, 100)
                    n_sim += 1.f;
                    s_sim += fminf(d, 100.f);
                } else {
                    // bce_disim = -max(log1p(-exp(-d)), -100)
                    float p = expf(-d);
                    float l = log1pf(-p);
                    n_dis += 1.f;
                    s_dis += -fmaxf(l, -100.f);
                }
            }
        }
    }

    // Warp reduce
#pragma unroll
    for (int off = 16; off > 0; off >>= 1) {
        n_sim += __shfl_down_sync(0xFFFFFFFFu, n_sim, off);
        n_dis += __shfl_down_sync(0xFFFFFFFFu, n_dis, off);
        s_sim += __shfl_down_sync(0xFFFFFFFFu, s_sim, off);
        s_dis += __shfl_down_sync(0xFFFFFFFFu, s_dis, off);
    }

    __shared__ float sh[4][8];
    int w = threadIdx.x >> 5;
    if (lane == 0) {
        sh[0][w] = n_sim;
        sh[1][w] = n_dis;
        sh[2][w] = s_sim;
        sh[3][w] = s_dis;
    }
    __syncthreads();

    if (w == 0 && lane < 8) {
        float a0 = sh[0][lane], a1 = sh[1][lane], a2 = sh[2][lane], a3 = sh[3][lane];
#pragma unroll
        for (int off = 4; off > 0; off >>= 1) {
            a0 += __shfl_down_sync(0xFFu, a0, off);
            a1 += __shfl_down_sync(0xFFu, a1, off);
            a2 += __shfl_down_sync(0xFFu, a2, off);
            a3 += __shfl_down_sync(0xFFu, a3, off);
        }
        if (lane == 0) {
            g_part[blockIdx.x][0] = (double)a0;
            g_part[blockIdx.x][1] = (double)a1;
            g_part[blockIdx.x][2] = (double)a2;
            g_part[blockIdx.x][3] = (double)a3;
        }
    }
}

__global__ void __launch_bounds__(256)
lp_finalize_kernel(float* out) {
    double a0 = 0.0, a1 = 0.0, a2 = 0.0, a3 = 0.0;
    for (int b = threadIdx.x; b < GRID_BLOCKS; b += 256) {
        a0 += g_part[b][0];
        a1 += g_part[b][1];
        a2 += g_part[b][2];
        a3 += g_part[b][3];
    }
    __shared__ double sh[4][32];
    int lane = threadIdx.x & 31, w = threadIdx.x >> 5;
#pragma unroll
    for (int off = 16; off > 0; off >>= 1) {
        a0 += __shfl_down_sync(0xFFFFFFFFu, a0, off);
        a1 += __shfl_down_sync(0xFFFFFFFFu, a1, off);
        a2 += __shfl_down_sync(0xFFFFFFFFu, a2, off);
        a3 += __shfl_down_sync(0xFFFFFFFFu, a3, off);
    }
    if (lane == 0) { sh[0][w] = a0; sh[1][w] = a1; sh[2][w] = a2; sh[3][w] = a3; }
    __syncthreads();
    if (threadIdx.x == 0) {
        double ns = 0, nd = 0, ss = 0, ds = 0;
        for (int k = 0; k < 8; k++) {
            ns += sh[0][k]; nd += sh[1][k]; ss += sh[2][k]; ds += sh[3][k];
        }
        double total = ns + nd;
        double loss = (ss * (nd / total) + ds * (ns / total)) / total;
        out[0] = (float)loss;
    }
}

extern "C" void kernel_launch(void* const* d_in, const int* in_sizes, int n_in,
                              void* d_out, int out_size) {
    // Identify inputs by element count (robust to metadata ordering):
    //   probas: n_nodes elements (smallest), feats: n_nodes*64, edges: rest.
    int idx_e = 0, idx_p = 1, idx_f = 2;
    if (n_in == 3) {
        int smallest = 0;
        for (int k = 1; k < 3; k++)
            if (in_sizes[k] < in_sizes[smallest]) smallest = k;
        int pf = -1, ee = -1;
        for (int k = 0; k < 3; k++) {
            if (k == smallest) continue;
            if (in_sizes[k] == in_sizes[smallest] * 64) pf = k;
            else ee = k;
        }
        if (pf >= 0 && ee >= 0) { idx_p = smallest; idx_f = pf; idx_e = ee; }
    }

    const void* edges = d_in[idx_e];
    const float* probas = (const float*)d_in[idx_p];
    const float* feats = (const float*)d_in[idx_f];
    float* out = (float*)d_out;

    int n_edges = in_sizes[idx_e] / 2;
    int n_nodes = in_sizes[idx_p];

    lp_edge_kernel<<<GRID_BLOCKS, BLOCK_THREADS>>>(edges, probas, feats,
                                                   n_edges, n_nodes);
    lp_finalize_kernel<<<1, 256>>>(out);
}

// round 5
// speedup vs baseline: 1.1635x; 1.1635x over previous
#include <cuda_runtime.h>
#include <cuda_bf16.h>

#define THR_LO 0.6f
#define THR_HI 0.8f

#define GRID_BLOCKS 1184   // 148 SMs * 8 CTAs of 256 = one full wave
#define BLOCK_THREADS 256

#define CLS_WORDS_CAP 8192        // 2-bit classes, up to 131072 nodes
#define SMEM_CLS_CAP 6592         // 25.75KB smem -> 8 blocks/SM still fits
#define SEG_CAP 1050000           // >= n_edges + GRID_BLOCKS for n<=1.04M

// class: 0 = p < THR_LO, 1 = mid, 2 = p >= THR_HI
__device__ unsigned g_cls[CLS_WORDS_CAP];
__device__ int2 g_seg[SEG_CAP];          // compacted masked edges (per-block segments)
__device__ int g_cnt[GRID_BLOCKS];       // masked count per block
__device__ float g_ns[GRID_BLOCKS], g_nd[GRID_BLOCKS];   // counts (k2)
__device__ float g_ss[GRID_BLOCKS], g_sd[GRID_BLOCKS];   // sums (k3)

// ---------------------------------------------------------------- k1: classes
__global__ void __launch_bounds__(256)
lp_class_kernel(const float* __restrict__ probas, int n_nodes) {
    int t = blockIdx.x * blockDim.x + threadIdx.x;
    int lane = threadIdx.x & 31;
    unsigned c = 1;  // OOB nodes -> mid (never matches)
    if (t < n_nodes) {
        float p = __ldg(&probas[t]);
        c = (p >= THR_HI) ? 2u : (p < THR_LO ? 0u : 1u);
    }
    unsigned v = c << ((lane & 15) * 2);
    v |= __shfl_xor_sync(0xFFFFFFFFu, v, 1);
    v |= __shfl_xor_sync(0xFFFFFFFFu, v, 2);
    v |= __shfl_xor_sync(0xFFFFFFFFu, v, 4);
    v |= __shfl_xor_sync(0xFFFFFFFFu, v, 8);
    int w = t >> 4;
    if ((lane & 15) == 0 && w < CLS_WORDS_CAP) g_cls[w] = v;
}

// --------------------------------------------------- k2: mask + compact edges
__global__ void __launch_bounds__(BLOCK_THREADS)
lp_compact_kernel(const void* __restrict__ edges,
                  int n_edges, int n_nodes, int chunk) {
    __shared__ unsigned s_cls[SMEM_CLS_CAP];
    __shared__ int s_cnt;
    __shared__ int s_is64;
    __shared__ float s_red[2][8];

    int tid = threadIdx.x;
    int cls_words = (n_nodes + 15) >> 4;
    bool use_smem = cls_words <= SMEM_CLS_CAP;
    if (use_smem)
        for (int w = tid; w < cls_words; w += BLOCK_THREADS) s_cls[w] = g_cls[w];
    if (tid == 0) {
        s_cnt = 0;
        // int64 edges: odd 32-bit words (high halves) are zero.
        const int4* hw = reinterpret_cast<const int4*>(edges);
        int4 a = __ldg(&hw[0]);
        int4 b = __ldg(&hw[1]);
        s_is64 = ((a.y | a.w | b.y | b.w) == 0) ? 1 : 0;
    }
    __syncthreads();
    const int is64 = s_is64;

    const longlong2* e64 = reinterpret_cast<const longlong2*>(edges);
    const int2* e32 = reinterpret_cast<const int2*>(edges);

    int beg = blockIdx.x * chunk;
    int end = min(beg + chunk, n_edges);
    int lane = tid & 31;
    int seg_base = blockIdx.x * chunk;

    float n_sim = 0.f, n_dis = 0.f;

    // eb is warp-uniform (tid & ~31): all 32 lanes iterate together.
    for (int eb = beg + (tid & ~31); eb < end; eb += BLOCK_THREADS) {
        int e = eb + lane;
        bool valid = e < end;
        int i = 0, j = 0;
        if (valid) {
            if (is64) { longlong2 ij = e64[e]; i = (int)ij.x; j = (int)ij.y; }
            else      { int2 ij = e32[e];      i = ij.x;      j = ij.y; }
        }
        if ((unsigned)i >= (unsigned)n_nodes || (unsigned)j >= (unsigned)n_nodes)
            valid = false;

        bool ms = false, md = false;
        if (valid) {
            unsigned ci, cj;
            if (use_smem) {
                ci = (s_cls[i >> 4] >> ((i & 15) << 1)) & 3u;
                cj = (s_cls[j >> 4] >> ((j & 15) << 1)) & 3u;
            } else {
                ci = (__ldg(&g_cls[i >> 4]) >> ((i & 15) << 1)) & 3u;
                cj = (__ldg(&g_cls[j >> 4]) >> ((j & 15) << 1)) & 3u;
            }
            ms = ((ci & cj) == 2u);   // both hi
            md = ((ci ^ cj) == 2u);   // {hi,lo} either order
        }
        n_sim += ms ? 1.f : 0.f;
        n_dis += md ? 1.f : 0.f;

        unsigned bal = __ballot_sync(0xFFFFFFFFu, ms | md);
        if (bal) {  // warp-uniform condition
            int base = 0;
            if (lane == 0) base = atomicAdd(&s_cnt, __popc(bal));
            base = __shfl_sync(0xFFFFFFFFu, base, 0);
            if (ms | md) {
                int pos = base + __popc(bal & ((1u << lane) - 1u));
                g_seg[seg_base + pos] =
                    make_int2(i | (ms ? (int)0x80000000 : 0), j);
            }
        }
    }

    // Block reduce counts
#pragma unroll
    for (int off = 16; off > 0; off >>= 1) {
        n_sim += __shfl_down_sync(0xFFFFFFFFu, n_sim, off);
        n_dis += __shfl_down_sync(0xFFFFFFFFu, n_dis, off);
    }
    int w = tid >> 5;
    if (lane == 0) { s_red[0][w] = n_sim; s_red[1][w] = n_dis; }
    __syncthreads();
    if (tid == 0) {
        float a0 = 0.f, a1 = 0.f;
        for (int k = 0; k < 8; k++) { a0 += s_red[0][k]; a1 += s_red[1][k]; }
        g_ns[blockIdx.x] = a0;
        g_nd[blockIdx.x] = a1;
        g_cnt[blockIdx.x] = s_cnt;
    }
}

// ------------------------------------------------- k3: dense distance + sums
__global__ void __launch_bounds__(BLOCK_THREADS)
lp_dist_kernel(const float* __restrict__ feats, int chunk) {
    int cnt = g_cnt[blockIdx.x];
    int seg_base = blockIdx.x * chunk;

    int tid = threadIdx.x;
    int lane = tid & 31;
    int w = tid >> 5;
    int half = lane >> 4;         // which edge of the pair this half handles
    int k = lane & 15;            // float4 chunk within the 64-elem row

    const float4* f4 = reinterpret_cast<const float4*>(feats);

    float s_sim = 0.f, s_dis = 0.f;

    // WARP-UNIFORM loop bound (p depends only on w): both halves always
    // execute the same iterations; the tail edge is predicated, never
    // diverging around the shfls.  (R4 hang fix.)
    for (int p = w; 2 * p < cnt; p += 8) {
        int it = 2 * p + half;
        bool act = it < cnt;

        int2 e = act ? g_seg[seg_base + it] : make_int2(0, 0);
        bool ms = e.x < 0;
        long long i = (long long)(e.x & 0x7FFFFFFF);
        long long j = (long long)e.y;

        float4 a, b;
        if (act) {
            a = __ldg(&f4[i * 16 + k]);
            b = __ldg(&f4[j * 16 + k]);
        } else {
            a = make_float4(0.f, 0.f, 0.f, 0.f);
            b = a;
        }
        float dx = a.x - b.x, dy = a.y - b.y, dz = a.z - b.z, dw = a.w - b.w;
        float s = fmaf(dx, dx, fmaf(dy, dy, fmaf(dz, dz, dw * dw)));

        // Reduce over the 16-lane half (xor offsets < 16 stay in-half).
        s += __shfl_xor_sync(0xFFFFFFFFu, s, 1);
        s += __shfl_xor_sync(0xFFFFFFFFu, s, 2);
        s += __shfl_xor_sync(0xFFFFFFFFu, s, 4);
        s += __shfl_xor_sync(0xFFFFFFFFu, s, 8);

        if (act && k == 0) {
            float d = sqrtf(s);
            if (ms) {
                s_sim += fminf(d, 100.f);                 // -max(log e^-d, -100)
            } else {
                float p2 = expf(-d);
                s_dis += -fmaxf(log1pf(-p2), -100.f);
            }
        }
    }

    __shared__ float s_red[2][8];
#pragma unroll
    for (int off = 16; off > 0; off >>= 1) {
        s_sim += __shfl_down_sync(0xFFFFFFFFu, s_sim, off);
        s_dis += __shfl_down_sync(0xFFFFFFFFu, s_dis, off);
    }
    if (lane == 0) { s_red[0][w] = s_sim; s_red[1][w] = s_dis; }
    __syncthreads();
    if (tid == 0) {
        float a0 = 0.f, a1 = 0.f;
        for (int q = 0; q < 8; q++) { a0 += s_red[0][q]; a1 += s_red[1][q]; }
        g_ss[blockIdx.x] = a0;
        g_sd[blockIdx.x] = a1;
    }
}

// ---------------------------------------------------------------- k4: final
__global__ void __launch_bounds__(256)
lp_finalize_kernel(float* out) {
    double a0 = 0, a1 = 0, a2 = 0, a3 = 0;
    for (int b = threadIdx.x; b < GRID_BLOCKS; b += 256) {
        a0 += (double)g_ns[b];
        a1 += (double)g_nd[b];
        a2 += (double)g_ss[b];
        a3 += (double)g_sd[b];
    }
    __shared__ double sh[4][8];
    int lane = threadIdx.x & 31, w = threadIdx.x >> 5;
#pragma unroll
    for (int off = 16; off > 0; off >>= 1) {
        a0 += __shfl_down_sync(0xFFFFFFFFu, a0, off);
        a1 += __shfl_down_sync(0xFFFFFFFFu, a1, off);
        a2 += __shfl_down_sync(0xFFFFFFFFu, a2, off);
        a3 += __shfl_down_sync(0xFFFFFFFFu, a3, off);
    }
    if (lane == 0) { sh[0][w] = a0; sh[1][w] = a1; sh[2][w] = a2; sh[3][w] = a3; }
    __syncthreads();
    if (threadIdx.x == 0) {
        double ns = 0, nd = 0, ss = 0, ds = 0;
        for (int q = 0; q < 8; q++) {
            ns += sh[0][q]; nd += sh[1][q]; ss += sh[2][q]; ds += sh[3][q];
        }
        double total = ns + nd;
        double loss = (ss * (nd / total) + ds * (ns / total)) / total;
        out[0] = (float)loss;
    }
}

extern "C" void kernel_launch(void* const* d_in, const int* in_sizes, int n_in,
                              void* d_out, int out_size) {
    // Identify inputs by element count (robust to metadata ordering):
    //   probas: n_nodes (smallest), feats: n_nodes*64, edges: the rest.
    int idx_e = 0, idx_p = 1, idx_f = 2;
    if (n_in == 3) {
        int smallest = 0;
        for (int k = 1; k < 3; k++)
            if (in_sizes[k] < in_sizes[smallest]) smallest = k;
        int pf = -1, ee = -1;
        for (int k = 0; k < 3; k++) {
            if (k == smallest) continue;
            if (in_sizes[k] == in_sizes[smallest] * 64) pf = k;
            else ee = k;
        }
        if (pf >= 0 && ee >= 0) { idx_p = smallest; idx_f = pf; idx_e = ee; }
    }

    const void* edges = d_in[idx_e];
    const float* probas = (const float*)d_in[idx_p];
    const float* feats = (const float*)d_in[idx_f];
    float* out = (float*)d_out;

    int n_edges = in_sizes[idx_e] / 2;
    int n_nodes = in_sizes[idx_p];
    int chunk = (n_edges + GRID_BLOCKS - 1) / GRID_BLOCKS;

    int cls_blocks = (n_nodes + 255) / 256;
    lp_class_kernel<<<cls_blocks, 256>>>(probas, n_nodes);
    lp_compact_kernel<<<GRID_BLOCKS, BLOCK_THREADS>>>(edges, n_edges, n_nodes,
                                                      chunk);
    lp_dist_kernel<<<GRID_BLOCKS, BLOCK_THREADS>>>(feats, chunk);
    lp_finalize_kernel<<<1, 256>>>(out);
}

// round 6
// speedup vs baseline: 1.3100x; 1.1258x over previous
#include <cuda_runtime.h>
#include <cuda_bf16.h>

#define THR_LO 0.6f
#define THR_HI 0.8f

#define GRID_BLOCKS 1036   // 148 SMs * 7 CTAs (smem-limited at ~30KB/CTA)
#define BLOCK_THREADS 256
#define NWARPS 8
#define RING 64            // per-warp masked-edge ring (power of 2)

#define CLS_WORDS_CAP 6592 // 2-bit classes, up to 105472 nodes

// class: 0 = p < THR_LO, 1 = mid, 2 = p >= THR_HI
__device__ unsigned g_cls[CLS_WORDS_CAP];
// Accumulators: n_sim, n_disim, sim_sum, disim_sum  (+ finish ticket)
__device__ double g_acc[4];
__device__ int g_done;

// ------------------------------------------- k1: classes + accumulator reset
__global__ void __launch_bounds__(256)
lp_class_kernel(const float* __restrict__ probas, int n_nodes) {
    if (blockIdx.x == 0 && threadIdx.x < 5) {
        if (threadIdx.x < 4) g_acc[threadIdx.x] = 0.0;
        else g_done = 0;
    }
    int t = blockIdx.x * blockDim.x + threadIdx.x;
    int lane = threadIdx.x & 31;
    unsigned c = 1;  // OOB nodes -> mid (never matches)
    if (t < n_nodes) {
        float p = __ldg(&probas[t]);
        c = (p >= THR_HI) ? 2u : (p < THR_LO ? 0u : 1u);
    }
    unsigned v = c << ((lane & 15) * 2);
    v |= __shfl_xor_sync(0xFFFFFFFFu, v, 1);
    v |= __shfl_xor_sync(0xFFFFFFFFu, v, 2);
    v |= __shfl_xor_sync(0xFFFFFFFFu, v, 4);
    v |= __shfl_xor_sync(0xFFFFFFFFu, v, 8);
    int w = t >> 4;
    if ((lane & 15) == 0 && w < CLS_WORDS_CAP) g_cls[w] = v;
}

// ------------------- k2: fused mask + warp-ring compact + distance + finalize
__global__ void __launch_bounds__(BLOCK_THREADS)
lp_fused_kernel(const void* __restrict__ edges,
                const float* __restrict__ feats,
                float* __restrict__ out,
                int n_edges, int n_nodes, int chunk) {
    __shared__ unsigned s_cls[CLS_WORDS_CAP];
    __shared__ int2 s_buf[NWARPS][RING];
    __shared__ int s_is64;
    __shared__ float s_red[4][NWARPS];
    __shared__ int s_last;

    int tid = threadIdx.x;
    int lane = tid & 31;
    int w = tid >> 5;
    int half = lane >> 4;     // 0/1: which edge of the pair in dense phase
    int kq = lane & 15;       // float4 chunk within the 64-elem row

    int cls_words = (n_nodes + 15) >> 4;
    bool use_smem = cls_words <= CLS_WORDS_CAP;
    if (use_smem)
        for (int q = tid; q < cls_words; q += BLOCK_THREADS) s_cls[q] = g_cls[q];
    if (tid == 0) {
        // int64 edges: odd 32-bit words (high halves of idx < 2^31) are zero.
        const int4* hw = reinterpret_cast<const int4*>(edges);
        int4 a = __ldg(&hw[0]);
        int4 b = __ldg(&hw[1]);
        s_is64 = ((a.y | a.w | b.y | b.w) == 0) ? 1 : 0;
    }
    __syncthreads();
    const int is64 = s_is64;

    const longlong2* e64 = reinterpret_cast<const longlong2*>(edges);
    const int2* e32 = reinterpret_cast<const int2*>(edges);
    const float4* f4 = reinterpret_cast<const float4*>(feats);

    int beg = blockIdx.x * chunk;
    int end = min(beg + chunk, n_edges);

    float n_sim = 0.f, n_dis = 0.f, s_sim = 0.f, s_dis = 0.f;
    int wcnt = 0;   // unprocessed entries in this warp's ring (warp-uniform)
    int head = 0;   // ring read position (warp-uniform)

    // Process 32 buffered masked edges densely (16 iters x 2 edges).
    auto flush32 = [&]() {
        __syncwarp();
#pragma unroll 4
        for (int t = 0; t < 16; t++) {
            int2 e = s_buf[w][(head + t * 2 + half) & (RING - 1)];
            bool ms = e.x < 0;
            int i = e.x & 0x7FFFFFFF;
            int j = e.y;
            float4 a = __ldg(&f4[(long long)i * 16 + kq]);
            float4 b = __ldg(&f4[(long long)j * 16 + kq]);
            float dx = a.x - b.x, dy = a.y - b.y;
            float dz = a.z - b.z, dw = a.w - b.w;
            float s = fmaf(dx, dx, fmaf(dy, dy, fmaf(dz, dz, dw * dw)));
            s += __shfl_xor_sync(0xFFFFFFFFu, s, 1);
            s += __shfl_xor_sync(0xFFFFFFFFu, s, 2);
            s += __shfl_xor_sync(0xFFFFFFFFu, s, 4);
            s += __shfl_xor_sync(0xFFFFFFFFu, s, 8);
            if (kq == 0) {
                float d = sqrtf(s);
                if (ms) s_sim += fminf(d, 100.f);   // -max(log e^-d, -100)
                else    s_dis += -fmaxf(log1pf(-expf(-d)), -100.f);
            }
        }
        head = (head + 32) & (RING - 1);
        wcnt -= 32;
    };

    // Scan loop: eb warp-uniform, all lanes iterate together.
    for (int eb = beg + (tid & ~31); eb < end; eb += BLOCK_THREADS) {
        int e = eb + lane;
        bool valid = e < end;
        int i = 0, j = 0;
        if (valid) {
            if (is64) { longlong2 ij = e64[e]; i = (int)ij.x; j = (int)ij.y; }
            else      { int2 ij = e32[e];      i = ij.x;      j = ij.y; }
        }
        if ((unsigned)i >= (unsigned)n_nodes || (unsigned)j >= (unsigned)n_nodes)
            valid = false;

        bool ms = false, md = false;
        if (valid) {
            unsigned ci, cj;
            if (use_smem) {
                ci = (s_cls[i >> 4] >> ((i & 15) << 1)) & 3u;
                cj = (s_cls[j >> 4] >> ((j & 15) << 1)) & 3u;
            } else {
                ci = (__ldg(&g_cls[i >> 4]) >> ((i & 15) << 1)) & 3u;
                cj = (__ldg(&g_cls[j >> 4]) >> ((j & 15) << 1)) & 3u;
            }
            ms = ((ci & cj) == 2u);   // both hi
            md = ((ci ^ cj) == 2u);   // {hi,lo} either order
        }
        n_sim += ms ? 1.f : 0.f;
        n_dis += md ? 1.f : 0.f;

        unsigned bal = __ballot_sync(0xFFFFFFFFu, ms | md);
        int rank = __popc(bal & ((1u << lane) - 1u));
        if (ms | md)
            s_buf[w][(head + wcnt + rank) & (RING - 1)] =
                make_int2(i | (ms ? (int)0x80000000 : 0), j);
        wcnt += __popc(bal);                      // warp-uniform
        if (wcnt >= 32) flush32();                // warp-uniform condition
    }

    // Tail: process remaining wcnt (< 32) entries, warp-uniform bound.
    if (wcnt > 0) {
        __syncwarp();
        for (int t = 0; t < wcnt; t += 2) {       // wcnt uniform
            int it = t + half;
            bool act = it < wcnt;
            int2 e = act ? s_buf[w][(head + it) & (RING - 1)] : make_int2(0, 0);
            bool ms = e.x < 0;
            int i = e.x & 0x7FFFFFFF;
            int j = e.y;
            float4 a = make_float4(0.f, 0.f, 0.f, 0.f), b = a;
            if (act) {
                a = __ldg(&f4[(long long)i * 16 + kq]);
                b = __ldg(&f4[(long long)j * 16 + kq]);
            }
            float dx = a.x - b.x, dy = a.y - b.y;
            float dz = a.z - b.z, dw = a.w - b.w;
            float s = fmaf(dx, dx, fmaf(dy, dy, fmaf(dz, dz, dw * dw)));
            s += __shfl_xor_sync(0xFFFFFFFFu, s, 1);
            s += __shfl_xor_sync(0xFFFFFFFFu, s, 2);
            s += __shfl_xor_sync(0xFFFFFFFFu, s, 4);
            s += __shfl_xor_sync(0xFFFFFFFFu, s, 8);
            if (act && kq == 0) {
                float d = sqrtf(s);
                if (ms) s_sim += fminf(d, 100.f);
                else    s_dis += -fmaxf(log1pf(-expf(-d)), -100.f);
            }
        }
    }

    // Block reduce 4 partials
#pragma unroll
    for (int off = 16; off > 0; off >>= 1) {
        n_sim += __shfl_down_sync(0xFFFFFFFFu, n_sim, off);
        n_dis += __shfl_down_sync(0xFFFFFFFFu, n_dis, off);
        s_sim += __shfl_down_sync(0xFFFFFFFFu, s_sim, off);
        s_dis += __shfl_down_sync(0xFFFFFFFFu, s_dis, off);
    }
    if (lane == 0) {
        s_red[0][w] = n_sim; s_red[1][w] = n_dis;
        s_red[2][w] = s_sim; s_red[3][w] = s_dis;
    }
    __syncthreads();

    if (tid == 0) {
        float a0 = 0.f, a1 = 0.f, a2 = 0.f, a3 = 0.f;
#pragma unroll
        for (int q = 0; q < NWARPS; q++) {
            a0 += s_red[0][q]; a1 += s_red[1][q];
            a2 += s_red[2][q]; a3 += s_red[3][q];
        }
        atomicAdd(&g_acc[0], (double)a0);
        atomicAdd(&g_acc[1], (double)a1);
        atomicAdd(&g_acc[2], (double)a2);
        atomicAdd(&g_acc[3], (double)a3);
        __threadfence();
        int ticket = atomicAdd(&g_done, 1);
        s_last = (ticket == gridDim.x - 1);
    }
    __syncthreads();

    // Last block to finish computes the loss (all atomics are visible
    // because every other block's fence precedes its ticket increment).
    if (s_last && tid == 0) {
        double ns = g_acc[0], nd = g_acc[1], ss = g_acc[2], ds = g_acc[3];
        double total = ns + nd;
        double loss = (ss * (nd / total) + ds * (ns / total)) / total;
        out[0] = (float)loss;
    }
}

extern "C" void kernel_launch(void* const* d_in, const int* in_sizes, int n_in,
                              void* d_out, int out_size) {
    // Identify inputs by element count (robust to metadata ordering):
    //   probas: n_nodes (smallest), feats: n_nodes*64, edges: the rest.
    int idx_e = 0, idx_p = 1, idx_f = 2;
    if (n_in == 3) {
        int smallest = 0;
        for (int k = 1; k < 3; k++)
            if (in_sizes[k] < in_sizes[smallest]) smallest = k;
        int pf = -1, ee = -1;
        for (int k = 0; k < 3; k++) {
            if (k == smallest) continue;
            if (in_sizes[k] == in_sizes[smallest] * 64) pf = k;
            else ee = k;
        }
        if (pf >= 0 && ee >= 0) { idx_p = smallest; idx_f = pf; idx_e = ee; }
    }

    const void* edges = d_in[idx_e];
    const float* probas = (const float*)d_in[idx_p];
    const float* feats = (const float*)d_in[idx_f];
    float* out = (float*)d_out;

    int n_edges = in_sizes[idx_e] / 2;
    int n_nodes = in_sizes[idx_p];
    int chunk = (n_edges + GRID_BLOCKS - 1) / GRID_BLOCKS;

    int cls_blocks = (n_nodes + 255) / 256;
    lp_class_kernel<<<cls_blocks, 256>>>(probas, n_nodes);
    lp_fused_kernel<<<GRID_BLOCKS, BLOCK_THREADS>>>(edges, feats, out,
                                                    n_edges, n_nodes, chunk);
}

// round 7
// speedup vs baseline: 1.5908x; 1.2144x over previous
#include <cuda_runtime.h>
#include <cuda_bf16.h>

#define THR_LO 0.6f
#define THR_HI 0.8f

#define GRID_BLOCKS 1184   // 148 SMs * 8
#define BLOCK_THREADS 256
#define NWARPS 8
#define RING 64            // per-warp masked-edge ring (power of 2)

// Accumulators: n_sim, n_disim, sim_sum, disim_sum  (+ finish ticket).
// Zero-initialized at module load; the LAST block of every launch resets
// them after computing the loss, so every graph replay starts from zero.
__device__ double g_acc[4];
__device__ int g_done;

__global__ void __launch_bounds__(BLOCK_THREADS)
lp_fused_kernel(const void* __restrict__ edges,
                const float* __restrict__ probas,
                const float* __restrict__ feats,
                float* __restrict__ out,
                int n_edges, int n_nodes, int chunk, int nblocks) {
    __shared__ int2 s_buf[NWARPS][RING];
    __shared__ int s_is64;
    __shared__ float s_red[4][NWARPS];
    __shared__ int s_last;

    int tid = threadIdx.x;
    int lane = tid & 31;
    int w = tid >> 5;
    int g = lane >> 3;        // dense phase: group 0..3 (one edge each)
    int q = lane & 7;         // float4 chunk index within group

    if (tid == 0) {
        // int64 edges: odd 32-bit words (high halves of idx < 2^31) are zero.
        const int4* hw = reinterpret_cast<const int4*>(edges);
        int4 a = __ldg(&hw[0]);
        int4 b = __ldg(&hw[1]);
        s_is64 = ((a.y | a.w | b.y | b.w) == 0) ? 1 : 0;
    }
    __syncthreads();
    const int is64 = s_is64;

    const longlong2* e64 = reinterpret_cast<const longlong2*>(edges);
    const int2* e32 = reinterpret_cast<const int2*>(edges);
    const float4* f4 = reinterpret_cast<const float4*>(feats);

    int beg = blockIdx.x * chunk;
    int end = min(beg + chunk, n_edges);

    float n_sim = 0.f, n_dis = 0.f, s_sim = 0.f, s_dis = 0.f;
    int wcnt = 0;   // unprocessed ring entries (warp-uniform)
    int head = 0;   // ring read position (warp-uniform)

    // Dense-process 32 buffered masked edges: 8 iters x 4 edges,
    // 8 lanes per edge, 3 xor-shfls per reduction.
    auto flush32 = [&]() {
        __syncwarp();
#pragma unroll 2
        for (int t = 0; t < 8; t++) {
            int2 ed = s_buf[w][(head + t * 4 + g) & (RING - 1)];
            bool ms = ed.x < 0;
            int i = ed.x & 0x7FFFFFFF;
            int j = ed.y;
            const float4* ri = f4 + (long long)i * 16;
            const float4* rj = f4 + (long long)j * 16;
            float4 a1 = __ldg(ri + q);
            float4 a2 = __ldg(ri + 8 + q);
            float4 b1 = __ldg(rj + q);
            float4 b2 = __ldg(rj + 8 + q);
            float dx = a1.x - b1.x, dy = a1.y - b1.y;
            float dz = a1.z - b1.z, dw = a1.w - b1.w;
            float s = fmaf(dx, dx, fmaf(dy, dy, fmaf(dz, dz, dw * dw)));
            dx = a2.x - b2.x; dy = a2.y - b2.y;
            dz = a2.z - b2.z; dw = a2.w - b2.w;
            s += fmaf(dx, dx, fmaf(dy, dy, fmaf(dz, dz, dw * dw)));
            // Reduce over the 8-lane group (xor offsets < 8 stay in-group).
            s += __shfl_xor_sync(0xFFFFFFFFu, s, 1);
            s += __shfl_xor_sync(0xFFFFFFFFu, s, 2);
            s += __shfl_xor_sync(0xFFFFFFFFu, s, 4);
            if (q == 0) {
                float d = sqrtf(s);
                if (ms) s_sim += fminf(d, 100.f);  // -max(log e^-d, -100)
                else    s_dis += -fmaxf(log1pf(-expf(-d)), -100.f);
            }
        }
        head = (head + 32) & (RING - 1);
        wcnt -= 32;
    };

    // Scan: eb warp-uniform so all 32 lanes iterate together.
    for (int eb = beg + (tid & ~31); eb < end; eb += BLOCK_THREADS) {
        int e = eb + lane;
        bool valid = e < end;
        int i = 0, j = 0;
        if (valid) {
            if (is64) { longlong2 ij = e64[e]; i = (int)ij.x; j = (int)ij.y; }
            else      { int2 ij = e32[e];      i = ij.x;      j = ij.y; }
        }
        if ((unsigned)i >= (unsigned)n_nodes || (unsigned)j >= (unsigned)n_nodes)
            valid = false;

        bool ms = false, md = false;
        if (valid) {
            float pi = __ldg(&probas[i]);
            float pj = __ldg(&probas[j]);
            ms = (pi >= THR_HI) && (pj >= THR_HI);
            md = ((pi >= THR_HI) && (pj < THR_LO)) ||
                 ((pj >= THR_HI) && (pi < THR_LO));
        }
        n_sim += ms ? 1.f : 0.f;
        n_dis += md ? 1.f : 0.f;

        unsigned bal = __ballot_sync(0xFFFFFFFFu, ms | md);
        int rank = __popc(bal & ((1u << lane) - 1u));
        if (ms | md)
            s_buf[w][(head + wcnt + rank) & (RING - 1)] =
                make_int2(i | (ms ? (int)0x80000000 : 0), j);
        wcnt += __popc(bal);                      // warp-uniform
        if (wcnt >= 32) flush32();                // warp-uniform condition
    }

    // Tail (< 32 entries): warp-uniform bound, predicated work, all lanes
    // execute the shfls (R4 lesson).
    if (wcnt > 0) {
        __syncwarp();
        for (int t = 0; t < wcnt; t += 4) {
            int it = t + g;
            bool act = it < wcnt;
            int2 ed = act ? s_buf[w][(head + it) & (RING - 1)]
                          : make_int2(0, 0);
            bool ms = ed.x < 0;
            int i = ed.x & 0x7FFFFFFF;
            int j = ed.y;
            float4 a1 = make_float4(0.f, 0.f, 0.f, 0.f);
            float4 a2 = a1, b1 = a1, b2 = a1;
            if (act) {
                const float4* ri = f4 + (long long)i * 16;
                const float4* rj = f4 + (long long)j * 16;
                a1 = __ldg(ri + q);  a2 = __ldg(ri + 8 + q);
                b1 = __ldg(rj + q);  b2 = __ldg(rj + 8 + q);
            }
            float dx = a1.x - b1.x, dy = a1.y - b1.y;
            float dz = a1.z - b1.z, dw = a1.w - b1.w;
            float s = fmaf(dx, dx, fmaf(dy, dy, fmaf(dz, dz, dw * dw)));
            dx = a2.x - b2.x; dy = a2.y - b2.y;
            dz = a2.z - b2.z; dw = a2.w - b2.w;
            s += fmaf(dx, dx, fmaf(dy, dy, fmaf(dz, dz, dw * dw)));
            s += __shfl_xor_sync(0xFFFFFFFFu, s, 1);
            s += __shfl_xor_sync(0xFFFFFFFFu, s, 2);
            s += __shfl_xor_sync(0xFFFFFFFFu, s, 4);
            if (act && q == 0) {
                float d = sqrtf(s);
                if (ms) s_sim += fminf(d, 100.f);
                else    s_dis += -fmaxf(log1pf(-expf(-d)), -100.f);
            }
        }
    }

    // Block reduce 4 partials
#pragma unroll
    for (int off = 16; off > 0; off >>= 1) {
        n_sim += __shfl_down_sync(0xFFFFFFFFu, n_sim, off);
        n_dis += __shfl_down_sync(0xFFFFFFFFu, n_dis, off);
        s_sim += __shfl_down_sync(0xFFFFFFFFu, s_sim, off);
        s_dis += __shfl_down_sync(0xFFFFFFFFu, s_dis, off);
    }
    if (lane == 0) {
        s_red[0][w] = n_sim; s_red[1][w] = n_dis;
        s_red[2][w] = s_sim; s_red[3][w] = s_dis;
    }
    __syncthreads();

    if (tid == 0) {
        float a0 = 0.f, a1 = 0.f, a2 = 0.f, a3 = 0.f;
#pragma unroll
        for (int k = 0; k < NWARPS; k++) {
            a0 += s_red[0][k]; a1 += s_red[1][k];
            a2 += s_red[2][k]; a3 += s_red[3][k];
        }
        atomicAdd(&g_acc[0], (double)a0);
        atomicAdd(&g_acc[1], (double)a1);
        atomicAdd(&g_acc[2], (double)a2);
        atomicAdd(&g_acc[3], (double)a3);
        __threadfence();
        int ticket = atomicAdd(&g_done, 1);
        s_last = (ticket == nblocks - 1);
    }
    __syncthreads();

    // Last block computes the loss, then resets state for the next replay.
    if (s_last && tid == 0) {
        double ns = g_acc[0], nd = g_acc[1], ss = g_acc[2], ds = g_acc[3];
        double total = ns + nd;
        double loss = (ss * (nd / total) + ds * (ns / total)) / total;
        out[0] = (float)loss;
        g_acc[0] = 0.0; g_acc[1] = 0.0; g_acc[2] = 0.0; g_acc[3] = 0.0;
        g_done = 0;
    }
}

extern "C" void kernel_launch(void* const* d_in, const int* in_sizes, int n_in,
                              void* d_out, int out_size) {
    // Identify inputs by element count (robust to metadata ordering):
    //   probas: n_nodes (smallest), feats: n_nodes*64, edges: the rest.
    int idx_e = 0, idx_p = 1, idx_f = 2;
    if (n_in == 3) {
        int smallest = 0;
        for (int k = 1; k < 3; k++)
            if (in_sizes[k] < in_sizes[smallest]) smallest = k;
        int pf = -1, ee = -1;
        for (int k = 0; k < 3; k++) {
            if (k == smallest) continue;
            if (in_sizes[k] == in_sizes[smallest] * 64) pf = k;
            else ee = k;
        }
        if (pf >= 0 && ee >= 0) { idx_p = smallest; idx_f = pf; idx_e = ee; }
    }

    const void* edges = d_in[idx_e];
    const float* probas = (const float*)d_in[idx_p];
    const float* feats = (const float*)d_in[idx_f];
    float* out = (float*)d_out;

    int n_edges = in_sizes[idx_e] / 2;
    int n_nodes = in_sizes[idx_p];
    int chunk = (n_edges + GRID_BLOCKS - 1) / GRID_BLOCKS;

    lp_fused_kernel<<<GRID_BLOCKS, BLOCK_THREADS>>>(
        edges, probas, feats, out, n_edges, n_nodes, chunk, GRID_BLOCKS);
}

// round 8
// speedup vs baseline: 1.6877x; 1.0609x over previous
#include <cuda_runtime.h>
#include <cuda_bf16.h>

#define THR_LO 0.6f
#define THR_HI 0.8f

#define GRID_BLOCKS 1184   // 148 SMs * 8
#define BLOCK_THREADS 256
#define NWARPS 8
#define RING 64            // per-warp masked-edge ring (power of 2)

// Accumulators: n_sim, n_disim, sim_sum, disim_sum  (+ finish ticket).
// Zero at module load; the LAST block of each launch resets them after
// computing the loss, so every graph replay starts from zero.
__device__ double g_acc[4];
__device__ int g_done;

__global__ void __launch_bounds__(BLOCK_THREADS)
lp_fused_kernel(const void* __restrict__ edges,
                const float* __restrict__ probas,
                const float* __restrict__ feats,
                float* __restrict__ out,
                int n_edges, int n_nodes, int chunk, int nblocks) {
    __shared__ int2 s_buf[NWARPS][RING];
    __shared__ int s_is64;
    __shared__ float s_red[4][NWARPS];
    __shared__ int s_last;

    int tid = threadIdx.x;
    int lane = tid & 31;
    int w = tid >> 5;
    int g = lane >> 3;        // dense phase: group 0..3 (one edge each)
    int q = lane & 7;         // float4 chunk index within group

    if (tid == 0) {
        // int64 edges: odd 32-bit words (high halves of idx < 2^31) are zero.
        const int4* hw = reinterpret_cast<const int4*>(edges);
        int4 a = __ldg(&hw[0]);
        int4 b = __ldg(&hw[1]);
        s_is64 = ((a.y | a.w | b.y | b.w) == 0) ? 1 : 0;
    }
    __syncthreads();
    const int is64 = s_is64;

    const longlong2* e64 = reinterpret_cast<const longlong2*>(edges);
    const int2* e32 = reinterpret_cast<const int2*>(edges);
    const float4* f4 = reinterpret_cast<const float4*>(feats);

    // Per-warp contiguous range: 4 batched sub-tiles of 32 per macro-iter.
    int beg = blockIdx.x * chunk;
    int end = min(beg + chunk, n_edges);
    int ws = (chunk + NWARPS - 1) / NWARPS;
    int wbeg = beg + w * ws;
    int wend = min(wbeg + ws, end);

    float n_sim = 0.f, n_dis = 0.f, s_sim = 0.f, s_dis = 0.f;
    int wcnt = 0;   // unprocessed ring entries (warp-uniform)
    int head = 0;   // ring read position (warp-uniform)

    // Dense-process 32 buffered masked edges: 4 iters x (2 edges per 8-lane
    // group). All 8 LDG.128 of a pair issued before any FMA; the two shfl
    // reduction chains are interleaved so their latencies overlap.
    auto flush32 = [&]() {
        __syncwarp();
#pragma unroll
        for (int t = 0; t < 8; t += 2) {
            int2 e0 = s_buf[w][(head + t * 4 + g) & (RING - 1)];
            int2 e1 = s_buf[w][(head + (t + 1) * 4 + g) & (RING - 1)];
            const float4* r0i = f4 + (long long)(e0.x & 0x7FFFFFFF) * 16;
            const float4* r0j = f4 + (long long)e0.y * 16;
            const float4* r1i = f4 + (long long)(e1.x & 0x7FFFFFFF) * 16;
            const float4* r1j = f4 + (long long)e1.y * 16;
            float4 a0 = __ldg(r0i + q);
            float4 c0 = __ldg(r0i + 8 + q);
            float4 b0 = __ldg(r0j + q);
            float4 d0 = __ldg(r0j + 8 + q);
            float4 a1 = __ldg(r1i + q);
            float4 c1 = __ldg(r1i + 8 + q);
            float4 b1 = __ldg(r1j + q);
            float4 d1 = __ldg(r1j + 8 + q);

            float x, y, z, v;
            x = a0.x - b0.x; y = a0.y - b0.y; z = a0.z - b0.z; v = a0.w - b0.w;
            float s0 = fmaf(x, x, fmaf(y, y, fmaf(z, z, v * v)));
            x = c0.x - d0.x; y = c0.y - d0.y; z = c0.z - d0.z; v = c0.w - d0.w;
            s0 += fmaf(x, x, fmaf(y, y, fmaf(z, z, v * v)));
            x = a1.x - b1.x; y = a1.y - b1.y; z = a1.z - b1.z; v = a1.w - b1.w;
            float s1 = fmaf(x, x, fmaf(y, y, fmaf(z, z, v * v)));
            x = c1.x - d1.x; y = c1.y - d1.y; z = c1.z - d1.z; v = c1.w - d1.w;
            s1 += fmaf(x, x, fmaf(y, y, fmaf(z, z, v * v)));

            // Interleaved 8-lane reductions (xor < 8 stays in-group).
            s0 += __shfl_xor_sync(0xFFFFFFFFu, s0, 1);
            s1 += __shfl_xor_sync(0xFFFFFFFFu, s1, 1);
            s0 += __shfl_xor_sync(0xFFFFFFFFu, s0, 2);
            s1 += __shfl_xor_sync(0xFFFFFFFFu, s1, 2);
            s0 += __shfl_xor_sync(0xFFFFFFFFu, s0, 4);
            s1 += __shfl_xor_sync(0xFFFFFFFFu, s1, 4);

            if (q == 0) {
                float d = sqrtf(s0);
                if (e0.x < 0) s_sim += fminf(d, 100.f);
                else          s_dis += -fmaxf(log1pf(-expf(-d)), -100.f);
                d = sqrtf(s1);
                if (e1.x < 0) s_sim += fminf(d, 100.f);
                else          s_dis += -fmaxf(log1pf(-expf(-d)), -100.f);
            }
        }
        head = (head + 32) & (RING - 1);
        wcnt -= 32;
    };

    // Scan: 128 edges per warp-iter, all loads batched for MLP.
    for (int mb = wbeg; mb < wend; mb += 128) {   // warp-uniform bound
        int ei[4], ej[4];
        bool val[4];
#pragma unroll
        for (int t = 0; t < 4; t++) {
            int e = mb + t * 32 + lane;
            val[t] = e < wend;
            int i = 0, j = 0;
            if (val[t]) {
                if (is64) { longlong2 ij = e64[e]; i = (int)ij.x; j = (int)ij.y; }
                else      { int2 ij = e32[e];      i = ij.x;      j = ij.y; }
            }
            if ((unsigned)i >= (unsigned)n_nodes ||
                (unsigned)j >= (unsigned)n_nodes) val[t] = false;
            ei[t] = val[t] ? i : 0;
            ej[t] = val[t] ? j : 0;
        }
        float pi[4], pj[4];
#pragma unroll
        for (int t = 0; t < 4; t++) {
            pi[t] = __ldg(&probas[ei[t]]);
            pj[t] = __ldg(&probas[ej[t]]);
        }
#pragma unroll
        for (int t = 0; t < 4; t++) {
            bool ms = false, md = false;
            if (val[t]) {
                ms = (pi[t] >= THR_HI) && (pj[t] >= THR_HI);
                md = ((pi[t] >= THR_HI) && (pj[t] < THR_LO)) ||
                     ((pj[t] >= THR_HI) && (pi[t] < THR_LO));
            }
            n_sim += ms ? 1.f : 0.f;
            n_dis += md ? 1.f : 0.f;

            unsigned bal = __ballot_sync(0xFFFFFFFFu, ms | md);
            int rank = __popc(bal & ((1u << lane) - 1u));
            if (ms | md)
                s_buf[w][(head + wcnt + rank) & (RING - 1)] =
                    make_int2(ei[t] | (ms ? (int)0x80000000 : 0), ej[t]);
            wcnt += __popc(bal);                  // warp-uniform
            if (wcnt >= 32) flush32();            // warp-uniform condition
        }
    }

    // Tail (< 32 entries): warp-uniform bound, predicated work, all lanes
    // run the shfls (R4 lesson).
    if (wcnt > 0) {
        __syncwarp();
        for (int t = 0; t < wcnt; t += 4) {
            int it = t + g;
            bool act = it < wcnt;
            int2 ed = act ? s_buf[w][(head + it) & (RING - 1)]
                          : make_int2(0, 0);
            bool ms = ed.x < 0;
            int i = ed.x & 0x7FFFFFFF;
            int j = ed.y;
            float4 a1 = make_float4(0.f, 0.f, 0.f, 0.f);
            float4 a2 = a1, b1 = a1, b2 = a1;
            if (act) {
                const float4* ri = f4 + (long long)i * 16;
                const float4* rj = f4 + (long long)j * 16;
                a1 = __ldg(ri + q);  a2 = __ldg(ri + 8 + q);
                b1 = __ldg(rj + q);  b2 = __ldg(rj + 8 + q);
            }
            float dx = a1.x - b1.x, dy = a1.y - b1.y;
            float dz = a1.z - b1.z, dw = a1.w - b1.w;
            float s = fmaf(dx, dx, fmaf(dy, dy, fmaf(dz, dz, dw * dw)));
            dx = a2.x - b2.x; dy = a2.y - b2.y;
            dz = a2.z - b2.z; dw = a2.w - b2.w;
            s += fmaf(dx, dx, fmaf(dy, dy, fmaf(dz, dz, dw * dw)));
            s += __shfl_xor_sync(0xFFFFFFFFu, s, 1);
            s += __shfl_xor_sync(0xFFFFFFFFu, s, 2);
            s += __shfl_xor_sync(0xFFFFFFFFu, s, 4);
            if (act && q == 0) {
                float d = sqrtf(s);
                if (ms) s_sim += fminf(d, 100.f);
                else    s_dis += -fmaxf(log1pf(-expf(-d)), -100.f);
            }
        }
    }

    // Block reduce 4 partials
#pragma unroll
    for (int off = 16; off > 0; off >>= 1) {
        n_sim += __shfl_down_sync(0xFFFFFFFFu, n_sim, off);
        n_dis += __shfl_down_sync(0xFFFFFFFFu, n_dis, off);
        s_sim += __shfl_down_sync(0xFFFFFFFFu, s_sim, off);
        s_dis += __shfl_down_sync(0xFFFFFFFFu, s_dis, off);
    }
    if (lane == 0) {
        s_red[0][w] = n_sim; s_red[1][w] = n_dis;
        s_red[2][w] = s_sim; s_red[3][w] = s_dis;
    }
    __syncthreads();

    if (tid == 0) {
        float a0 = 0.f, a1 = 0.f, a2 = 0.f, a3 = 0.f;
#pragma unroll
        for (int k = 0; k < NWARPS; k++) {
            a0 += s_red[0][k]; a1 += s_red[1][k];
            a2 += s_red[2][k]; a3 += s_red[3][k];
        }
        atomicAdd(&g_acc[0], (double)a0);
        atomicAdd(&g_acc[1], (double)a1);
        atomicAdd(&g_acc[2], (double)a2);
        atomicAdd(&g_acc[3], (double)a3);
        __threadfence();
        int ticket = atomicAdd(&g_done, 1);
        s_last = (ticket == nblocks - 1);
    }
    __syncthreads();

    // Last block computes the loss, then resets state for the next replay.
    if (s_last && tid == 0) {
        double ns = g_acc[0], nd = g_acc[1], ss = g_acc[2], ds = g_acc[3];
        double total = ns + nd;
        double loss = (ss * (nd / total) + ds * (ns / total)) / total;
        out[0] = (float)loss;
        g_acc[0] = 0.0; g_acc[1] = 0.0; g_acc[2] = 0.0; g_acc[3] = 0.0;
        g_done = 0;
    }
}

extern "C" void kernel_launch(void* const* d_in, const int* in_sizes, int n_in,
                              void* d_out, int out_size) {
    // Identify inputs by element count (robust to metadata ordering):
    //   probas: n_nodes (smallest), feats: n_nodes*64, edges: the rest.
    int idx_e = 0, idx_p = 1, idx_f = 2;
    if (n_in == 3) {
        int smallest = 0;
        for (int k = 1; k < 3; k++)
            if (in_sizes[k] < in_sizes[smallest]) smallest = k;
        int pf = -1, ee = -1;
        for (int k = 0; k < 3; k++) {
            if (k == smallest) continue;
            if (in_sizes[k] == in_sizes[smallest] * 64) pf = k;
            else ee = k;
        }
        if (pf >= 0 && ee >= 0) { idx_p = smallest; idx_f = pf; idx_e = ee; }
    }

    const void* edges = d_in[idx_e];
    const float* probas = (const float*)d_in[idx_p];
    const float* feats = (const float*)d_in[idx_f];
    float* out = (float*)d_out;

    int n_edges = in_sizes[idx_e] / 2;
    int n_nodes = in_sizes[idx_p];
    int chunk = (n_edges + GRID_BLOCKS - 1) / GRID_BLOCKS;

    lp_fused_kernel<<<GRID_BLOCKS, BLOCK_THREADS>>>(
        edges, probas, feats, out, n_edges, n_nodes, chunk, GRID_BLOCKS);
}

// round 10
// speedup vs baseline: 1.9583x; 1.1604x over previous
#include <cuda_runtime.h>
#include <cuda_bf16.h>

#define THR_LO 0.6f
#define THR_HI 0.8f

#define GRID_BLOCKS 592    // 148 SMs * 4 resident (56 regs) = ONE full wave
#define BLOCK_THREADS 256
#define NWARPS 8
#define RING 64            // per-warp masked-edge ring (power of 2)

// Accumulators: n_sim, n_disim, sim_sum, disim_sum  (+ finish ticket).
// Zero at module load; the LAST block of each launch resets them after
// computing the loss, so every graph replay starts from zero.
__device__ double g_acc[4];
__device__ int g_done;

__global__ void __launch_bounds__(BLOCK_THREADS)
lp_fused_kernel(const void* __restrict__ edges,
                const float* __restrict__ probas,
                const float* __restrict__ feats,
                float* __restrict__ out,
                int n_edges, int n_nodes, int chunk, int nblocks) {
    __shared__ int2 s_buf[NWARPS][RING];
    __shared__ int s_is64;
    __shared__ float s_red[4][NWARPS];
    __shared__ int s_last;

    int tid = threadIdx.x;
    int lane = tid & 31;
    int w = tid >> 5;
    int g = lane >> 3;        // dense phase: group 0..3 (one edge each)
    int q = lane & 7;         // float4 chunk index within group

    if (tid == 0) {
        // int64 edges: odd 32-bit words (high halves of idx < 2^31) are zero.
        const int4* hw = reinterpret_cast<const int4*>(edges);
        int4 a = __ldg(&hw[0]);
        int4 b = __ldg(&hw[1]);
        s_is64 = ((a.y | a.w | b.y | b.w) == 0) ? 1 : 0;
    }
    __syncthreads();
    const int is64 = s_is64;

    const longlong2* e64 = reinterpret_cast<const longlong2*>(edges);
    const int2* e32 = reinterpret_cast<const int2*>(edges);
    const char* fbase = reinterpret_cast<const char*>(feats);
    // Row i starts at byte i << 8 (64 floats * 4B = 256B per row).
    // Max offset ~25.6MB, fits 32-bit arithmetic comfortably.
    const unsigned qoff1 = (unsigned)q * 16u;        // bytes 0..112
    const unsigned qoff2 = qoff1 + 128u;             // bytes 128..240

    // Per-warp contiguous range: 4 batched sub-tiles of 32 per macro-iter.
    int beg = blockIdx.x * chunk;
    int end = min(beg + chunk, n_edges);
    int ws = (chunk + NWARPS - 1) / NWARPS;
    int wbeg = beg + w * ws;
    int wend = min(wbeg + ws, end);

    float n_sim = 0.f, n_dis = 0.f, s_sim = 0.f, s_dis = 0.f;
    int wcnt = 0;   // unprocessed ring entries (warp-uniform)
    int head = 0;   // ring read position (warp-uniform)

    auto ld4 = [&](unsigned byte_off) {
        return __ldg(reinterpret_cast<const float4*>(fbase + byte_off));
    };

    // Dense-process 32 buffered masked edges: pairs of 4-edge passes with all
    // 8 LDG.128 issued before any FMA; two shfl chains interleaved.
    auto flush32 = [&]() {
        __syncwarp();
#pragma unroll
        for (int t = 0; t < 8; t += 2) {
            int2 e0 = s_buf[w][(head + t * 4 + g) & (RING - 1)];
            int2 e1 = s_buf[w][(head + (t + 1) * 4 + g) & (RING - 1)];
            unsigned o0i = (unsigned)(e0.x & 0x7FFFFFFF) << 8;
            unsigned o0j = (unsigned)e0.y << 8;
            unsigned o1i = (unsigned)(e1.x & 0x7FFFFFFF) << 8;
            unsigned o1j = (unsigned)e1.y << 8;
            float4 a0 = ld4(o0i + qoff1);
            float4 c0 = ld4(o0i + qoff2);
            float4 b0 = ld4(o0j + qoff1);
            float4 d0 = ld4(o0j + qoff2);
            float4 a1 = ld4(o1i + qoff1);
            float4 c1 = ld4(o1i + qoff2);
            float4 b1 = ld4(o1j + qoff1);
            float4 d1 = ld4(o1j + qoff2);

            float x, y, z, v;
            x = a0.x - b0.x; y = a0.y - b0.y; z = a0.z - b0.z; v = a0.w - b0.w;
            float s0 = fmaf(x, x, fmaf(y, y, fmaf(z, z, v * v)));
            x = c0.x - d0.x; y = c0.y - d0.y; z = c0.z - d0.z; v = c0.w - d0.w;
            s0 += fmaf(x, x, fmaf(y, y, fmaf(z, z, v * v)));
            x = a1.x - b1.x; y = a1.y - b1.y; z = a1.z - b1.z; v = a1.w - b1.w;
            float s1 = fmaf(x, x, fmaf(y, y, fmaf(z, z, v * v)));
            x = c1.x - d1.x; y = c1.y - d1.y; z = c1.z - d1.z; v = c1.w - d1.w;
            s1 += fmaf(x, x, fmaf(y, y, fmaf(z, z, v * v)));

            s0 += __shfl_xor_sync(0xFFFFFFFFu, s0, 1);
            s1 += __shfl_xor_sync(0xFFFFFFFFu, s1, 1);
            s0 += __shfl_xor_sync(0xFFFFFFFFu, s0, 2);
            s1 += __shfl_xor_sync(0xFFFFFFFFu, s1, 2);
            s0 += __shfl_xor_sync(0xFFFFFFFFu, s0, 4);
            s1 += __shfl_xor_sync(0xFFFFFFFFu, s1, 4);

            if (q == 0) {
                float d = sqrtf(s0);
                if (e0.x < 0) s_sim += fminf(d, 100.f);
                else          s_dis += -fmaxf(log1pf(-expf(-d)), -100.f);
                d = sqrtf(s1);
                if (e1.x < 0) s_sim += fminf(d, 100.f);
                else          s_dis += -fmaxf(log1pf(-expf(-d)), -100.f);
            }
        }
        head = (head + 32) & (RING - 1);
        wcnt -= 32;
    };

    // Scan: 128 edges per warp-iter, all loads batched for MLP.
    for (int mb = wbeg; mb < wend; mb += 128) {   // warp-uniform bound
        int ei[4], ej[4];
        bool val[4];
#pragma unroll
        for (int t = 0; t < 4; t++) {
            int e = mb + t * 32 + lane;
            val[t] = e < wend;
            int i = 0, j = 0;
            if (val[t]) {
                if (is64) { longlong2 ij = e64[e]; i = (int)ij.x; j = (int)ij.y; }
                else      { int2 ij = e32[e];      i = ij.x;      j = ij.y; }
            }
            if ((unsigned)i >= (unsigned)n_nodes ||
                (unsigned)j >= (unsigned)n_nodes) val[t] = false;
            ei[t] = val[t] ? i : 0;
            ej[t] = val[t] ? j : 0;
        }
        float pi[4], pj[4];
#pragma unroll
        for (int t = 0; t < 4; t++) {
            pi[t] = __ldg(&probas[ei[t]]);
            pj[t] = __ldg(&probas[ej[t]]);
        }
#pragma unroll
        for (int t = 0; t < 4; t++) {
            bool ms = false, md = false;
            if (val[t]) {
                ms = (pi[t] >= THR_HI) && (pj[t] >= THR_HI);
                md = ((pi[t] >= THR_HI) && (pj[t] < THR_LO)) ||
                     ((pj[t] >= THR_HI) && (pi[t] < THR_LO));
            }
            n_sim += ms ? 1.f : 0.f;
            n_dis += md ? 1.f : 0.f;

            unsigned bal = __ballot_sync(0xFFFFFFFFu, ms | md);
            int rank = __popc(bal & ((1u << lane) - 1u));
            if (ms | md)
                s_buf[w][(head + wcnt + rank) & (RING - 1)] =
                    make_int2(ei[t] | (ms ? (int)0x80000000 : 0), ej[t]);
            wcnt += __popc(bal);                  // warp-uniform
            if (wcnt >= 32) flush32();            // warp-uniform condition
        }
    }

    // Tail (< 32 entries): warp-uniform bound, predicated work, all lanes
    // run the shfls (R4 lesson).
    if (wcnt > 0) {
        __syncwarp();
        for (int t = 0; t < wcnt; t += 4) {
            int it = t + g;
            bool act = it < wcnt;
            int2 ed = act ? s_buf[w][(head + it) & (RING - 1)]
                          : make_int2(0, 0);
            bool ms = ed.x < 0;
            unsigned oi = (unsigned)(ed.x & 0x7FFFFFFF) << 8;
            unsigned oj = (unsigned)ed.y << 8;
            float4 a1 = make_float4(0.f, 0.f, 0.f, 0.f);
            float4 a2 = a1, b1 = a1, b2 = a1;
            if (act) {
                a1 = ld4(oi + qoff1);  a2 = ld4(oi + qoff2);
                b1 = ld4(oj + qoff1);  b2 = ld4(oj + qoff2);
            }
            float dx = a1.x - b1.x, dy = a1.y - b1.y;
            float dz = a1.z - b1.z, dw = a1.w - b1.w;
            float s = fmaf(dx, dx, fmaf(dy, dy, fmaf(dz, dz, dw * dw)));
            dx = a2.x - b2.x; dy = a2.y - b2.y;
            dz = a2.z - b2.z; dw = a2.w - b2.w;
            s += fmaf(dx, dx, fmaf(dy, dy, fmaf(dz, dz, dw * dw)));
            s += __shfl_xor_sync(0xFFFFFFFFu, s, 1);
            s += __shfl_xor_sync(0xFFFFFFFFu, s, 2);
            s += __shfl_xor_sync(0xFFFFFFFFu, s, 4);
            if (act && q == 0) {
                float d = sqrtf(s);
                if (ms) s_sim += fminf(d, 100.f);
                else    s_dis += -fmaxf(log1pf(-expf(-d)), -100.f);
            }
        }
    }

    // Block reduce 4 partials
#pragma unroll
    for (int off = 16; off > 0; off >>= 1) {
        n_sim += __shfl_down_sync(0xFFFFFFFFu, n_sim, off);
        n_dis += __shfl_down_sync(0xFFFFFFFFu, n_dis, off);
        s_sim += __shfl_down_sync(0xFFFFFFFFu, s_sim, off);
        s_dis += __shfl_down_sync(0xFFFFFFFFu, s_dis, off);
    }
    if (lane == 0) {
        s_red[0][w] = n_sim; s_red[1][w] = n_dis;
        s_red[2][w] = s_sim; s_red[3][w] = s_dis;
    }
    __syncthreads();

    if (tid == 0) {
        float a0 = 0.f, a1 = 0.f, a2 = 0.f, a3 = 0.f;
#pragma unroll
        for (int k = 0; k < NWARPS; k++) {
            a0 += s_red[0][k]; a1 += s_red[1][k];
            a2 += s_red[2][k]; a3 += s_red[3][k];
        }
        atomicAdd(&g_acc[0], (double)a0);
        atomicAdd(&g_acc[1], (double)a1);
        atomicAdd(&g_acc[2], (double)a2);
        atomicAdd(&g_acc[3], (double)a3);
        __threadfence();
        int ticket = atomicAdd(&g_done, 1);
        s_last = (ticket == nblocks - 1);
    }
    __syncthreads();

    // Last block computes the loss, then resets state for the next replay.
    if (s_last && tid == 0) {
        double ns = g_acc[0], nd = g_acc[1], ss = g_acc[2], ds = g_acc[3];
        double total = ns + nd;
        double loss = (ss * (nd / total) + ds * (ns / total)) / total;
        out[0] = (float)loss;
        g_acc[0] = 0.0; g_acc[1] = 0.0; g_acc[2] = 0.0; g_acc[3] = 0.0;
        g_done = 0;
    }
}

extern "C" void kernel_launch(void* const* d_in, const int* in_sizes, int n_in,
                              void* d_out, int out_size) {
    // Identify inputs by element count (robust to metadata ordering):
    //   probas: n_nodes (smallest), feats: n_nodes*64, edges: the rest.
    int idx_e = 0, idx_p = 1, idx_f = 2;
    if (n_in == 3) {
        int smallest = 0;
        for (int k = 1; k < 3; k++)
            if (in_sizes[k] < in_sizes[smallest]) smallest = k;
        int pf = -1, ee = -1;
        for (int k = 0; k < 3; k++) {
            if (k == smallest) continue;
            if (in_sizes[k] == in_sizes[smallest] * 64) pf = k;
            else ee = k;
        }
        if (pf >= 0 && ee >= 0) { idx_p = smallest; idx_f = pf; idx_e = ee; }
    }

    const void* edges = d_in[idx_e];
    const float* probas = (const float*)d_in[idx_p];
    const float* feats = (const float*)d_in[idx_f];
    float* out = (float*)d_out;

    int n_edges = in_sizes[idx_e] / 2;
    int n_nodes = in_sizes[idx_p];
    int chunk = (n_edges + GRID_BLOCKS - 1) / GRID_BLOCKS;

    lp_fused_kernel<<<GRID_BLOCKS, BLOCK_THREADS>>>(
        edges, probas, feats, out, n_edges, n_nodes, chunk, GRID_BLOCKS);
}